// round 9
// baseline (speedup 1.0000x reference)
#include <cuda_runtime.h>

// Problem constants
#define Bsz   16
#define Lseq  4096
#define Dd    512
#define SPB   8          // d-lanes per tile = 4 float2 pairs
#define NSP   4          // sequence-pairs per tile
#define CH    32         // chunk length per thread
#define NCH   128        // chunks per sequence
#define NTH   512        // NSP * NCH
#define YSTRU 33         // padded per-thread stride in Y (ull units)
#define TILES (Bsz*(Dd/SPB))   // 1024

typedef unsigned long long ull;

// smem (ull): Yu + RRu(64) + VWT(128) + SWT(128) + XE(2*NTH) + CVu(8) + PWf/PKf(32 fl = 4)
#define SMEM_ULL (NTH*YSTRU + 64 + 128 + 128 + 2*NTH + 8 + 4 + 8)

__device__ __forceinline__ ull pk2(float lo, float hi) {
    ull r; asm("mov.b64 %0, {%1, %2};" : "=l"(r) : "f"(lo), "f"(hi)); return r;
}
__device__ __forceinline__ ull bc2(float v) { return pk2(v, v); }
__device__ __forceinline__ ull fma2(ull a, ull b, ull c) {
    ull d; asm("fma.rn.f32x2 %0, %1, %2, %3;" : "=l"(d) : "l"(a), "l"(b), "l"(c)); return d;
}
__device__ __forceinline__ ull mul2(ull a, ull b) {
    ull d; asm("mul.rn.f32x2 %0, %1, %2;" : "=l"(d) : "l"(a), "l"(b)); return d;
}
__device__ __forceinline__ void stcs64(ull* p, ull v) {
    asm volatile("st.global.cs.b64 [%0], %1;" :: "l"(p), "l"(v) : "memory");
}

__global__ void __launch_bounds__(NTH, 1)
iir_filtfilt_kernel(const float* __restrict__ x,
                    const float* __restrict__ bc,
                    const float* __restrict__ am,
                    float* __restrict__ out)
{
    extern __shared__ ull smu[];
    ull*   Yu  = smu;                         // NTH*YSTRU : x pairs (for trend)
    ull*   RRu = Yu + NTH * YSTRU;            // 64 : RRu[2i]=bcast(r0(A^(i+1))), [2i+1]=bcast(r1)
    ull*   VWT = RRu + 64;                    // 128 : warp aggregates [sp][w][2]
    ull*   SWT = VWT + 128;                   // 128 : warp start states
    ull*   XE  = SWT + 128;                   // 2*NTH : x-halos then y-edges
    ull*   CVu = XE + 2 * NTH;                // 8 : fwd(4)+bwd(4) boundary states
    float* PWf = (float*)(CVu + 8);           // 28 : A^32..A^224 (7 mats)
    float* PKf = PWf + 28;                    // 4  : A^256

    const int tid  = threadIdx.x;
    const int lane = tid & 31;
    const int wrp  = tid >> 5;                // 0..15
    const int sp   = tid & 3;                 // seq-pair 0..3
    const int ch   = tid >> 2;                // chunk 0..127
    const int g    = lane >> 2;               // chunk-in-warp 0..7

    const float b0s  = bc[0], b1s = bc[1], b2s = bc[2];
    const float na1s = am[0], na2s = am[1];   // A row0 = (-a1,-a2)
    const ull b0p  = bc2(b0s),  b1p = bc2(b1s), b2p = bc2(b2s);
    const ull na1p = bc2(na1s), na2p = bc2(na2s);
    const ull bsump = bc2(b0s + b1s + b2s);
    const ull neg1p = bc2(-1.0f);

    // Thread 0: RR table (packed-duplicated), PWf = A^32..A^224, PKf = A^256.
    if (tid == 0) {
        float p00 = na1s, p01 = na2s, p10 = 1.f, p11 = 0.f;   // A^1
        RRu[0] = bc2(p00); RRu[1] = bc2(p01);
        for (int i = 1; i < CH; ++i) {
            float q00 = fmaf(na1s, p00, na2s * p10);
            float q01 = fmaf(na1s, p01, na2s * p11);
            p10 = p00; p11 = p01; p00 = q00; p01 = q01;
            RRu[2*i] = bc2(p00); RRu[2*i+1] = bc2(p01);
        }
        float a00 = p00, a01 = p01, a10 = p10, a11 = p11;     // A^32
        float c00 = a00, c01 = a01, c10 = a10, c11 = a11;
        PWf[0] = c00; PWf[1] = c01; PWf[2] = c10; PWf[3] = c11;
        for (int k = 1; k < 7; ++k) {
            float n00 = c00*a00 + c01*a10, n01 = c00*a01 + c01*a11;
            float n10 = c10*a00 + c11*a10, n11 = c10*a01 + c11*a11;
            c00 = n00; c01 = n01; c10 = n10; c11 = n11;
            PWf[4*k] = c00; PWf[4*k+1] = c01; PWf[4*k+2] = c10; PWf[4*k+3] = c11;
        }
        // A^256 = A^224 * A^32
        PKf[0] = c00*a00 + c01*a10; PKf[1] = c00*a01 + c01*a11;
        PKf[2] = c10*a00 + c11*a10; PKf[3] = c10*a01 + c11*a11;
    }

    const size_t OUTT = (size_t)Bsz * Lseq * Dd;
    const size_t RS   = Dd / 2;               // row stride in ull

    for (int t = blockIdx.x; t < TILES; t += gridDim.x) {
        const int b  = t >> 6;
        const int d0 = (t & 63) * SPB;
        const ull* xpu = (const ull*)(x + (size_t)b * Lseq * Dd
                                        + (size_t)ch * CH * Dd + d0 + 2 * sp);

        // Load own chunk-pair to registers (LDG.64, front-batched).
        ull xr[CH];
        #pragma unroll
        for (int i = 0; i < CH; ++i) xr[i] = xpu[(size_t)i * RS];

        __syncthreads();    // B1: previous tile finished reading Yu/XE/CVu/SWT

        #pragma unroll
        for (int i = 0; i < CH; ++i) Yu[tid * YSTRU + i] = xr[i];
        XE[2 * tid]     = xr[CH - 2];         // x halos for next chunk
        XE[2 * tid + 1] = xr[CH - 1];
        if (ch == 0) CVu[sp] = mul2(bsump, xr[0]);   // c_fwd pair
        __syncthreads();    // B2

        // Next-tile prefetch base (deduped: 1 prefetch per 32B sector).
        int t2 = t + gridDim.x;  if (t2 >= TILES) t2 = t;
        const float* xpn = x + (size_t)(t2 >> 6) * Lseq * Dd
                             + (size_t)ch * CH * Dd + ((t2 & 63) * SPB);

        // ---------------- forward zero-init scan (p0 -> xr) ------------------
        ull xm1, xm2;
        if (ch == 0) { xm1 = xr[0]; xm2 = xr[0]; }
        else { xm1 = XE[2*(tid-NSP)+1]; xm2 = XE[2*(tid-NSP)]; }
        ull s0 = 0ull, s1 = 0ull;
        #pragma unroll
        for (int i = 0; i < CH; ++i) {
            if ((i & 3) == sp)
                asm volatile("prefetch.global.L2 [%0];" :: "l"(xpn + (size_t)i * Dd));
            ull bx = fma2(b2p, xm2, fma2(b1p, xm1, mul2(b0p, xr[i])));
            xm2 = xm1; xm1 = xr[i];
            ull ns = fma2(na1p, s0, fma2(na2p, s1, bx));
            s1 = s0; s0 = ns;
            xr[i] = ns;
        }

        // Intra-warp KS over 8 chunks/seq-pair: hops 1,2,4 chunks (A^32,A^64,A^128).
        ull v0 = s0, v1 = s1;
        {
            #pragma unroll
            for (int st = 0; st < 3; ++st) {
                const int hc = 1 << st;               // hop in chunks
                const float* M = PWf + 4 * (hc - 1);  // A^(32*hc): idx 0,1,3
                ull m00 = bc2(M[0]), m01 = bc2(M[1]), m10 = bc2(M[2]), m11 = bc2(M[3]);
                ull u0 = __shfl_up_sync(0xffffffffu, v0, 4 * hc);
                ull u1 = __shfl_up_sync(0xffffffffu, v1, 4 * hc);
                if (g < hc) { u0 = 0ull; u1 = 0ull; }
                v0 = fma2(m00, u0, fma2(m01, u1, v0));
                v1 = fma2(m10, u0, fma2(m11, u1, v1));
            }
        }
        ull E0 = __shfl_up_sync(0xffffffffu, v0, 4);
        ull E1 = __shfl_up_sync(0xffffffffu, v1, 4);
        if (g == 0) { E0 = 0ull; E1 = 0ull; }
        if (g == 7) {
            VWT[(sp * 16 + wrp) * 2]     = v0;
            VWT[(sp * 16 + wrp) * 2 + 1] = v1;
        }
        __syncthreads();    // B3

        // Inter-warp combine: T_w = v_{w-1} + A^256 * v_{w-2} (+A^512 terms ~3e-21 dropped).
        if (wrp < 4) {
            int spx = wrp;
            ull w0 = 0ull, w1 = 0ull;
            if (lane < 16) {
                w0 = VWT[(spx * 16 + lane) * 2];
                w1 = VWT[(spx * 16 + lane) * 2 + 1];
            }
            ull cpk = CVu[spx];
            ull a0 = __shfl_up_sync(0xffffffffu, w0, 1);
            ull a1 = __shfl_up_sync(0xffffffffu, w1, 1);
            ull q0 = __shfl_up_sync(0xffffffffu, w0, 2);
            ull q1 = __shfl_up_sync(0xffffffffu, w1, 2);
            if (lane == 1) { q0 = cpk; q1 = cpk; }
            ull m00 = bc2(PKf[0]), m01 = bc2(PKf[1]), m10 = bc2(PKf[2]), m11 = bc2(PKf[3]);
            ull T0 = fma2(m00, q0, fma2(m01, q1, a0));
            ull T1 = fma2(m10, q0, fma2(m11, q1, a1));
            if (lane == 0) { T0 = cpk; T1 = cpk; }
            if (lane < 16) {
                SWT[(spx * 16 + lane) * 2]     = T0;
                SWT[(spx * 16 + lane) * 2 + 1] = T1;
            }
        }
        __syncthreads();    // B4

        // Forward start state: ss = A^(32g)*T_w + E_g ; publish y-edges.
        ull ss0, ss1;
        {
            ull T0 = SWT[(sp * 16 + wrp) * 2], T1 = SWT[(sp * 16 + wrp) * 2 + 1];
            if (g == 0) { ss0 = T0; ss1 = T1; }
            else {
                const float* P = PWf + 4 * (g - 1);
                ss0 = fma2(bc2(P[0]), T0, fma2(bc2(P[1]), T1, E0));
                ss1 = fma2(bc2(P[2]), T0, fma2(bc2(P[3]), T1, E1));
            }
        }
        ull ylast = 0ull;
        {
            ull y0 = fma2(RRu[0], ss0, fma2(RRu[1], ss1, xr[0]));
            ull y1 = fma2(RRu[2], ss0, fma2(RRu[3], ss1, xr[1]));
            XE[2 * tid]     = y0;
            XE[2 * tid + 1] = y1;
            if (ch == NCH - 1) {
                ylast = fma2(RRu[2*(CH-1)], ss0, fma2(RRu[2*(CH-1)+1], ss1, xr[CH-1]));
                CVu[4 + sp] = mul2(bsump, ylast);
            }
        }
        __syncthreads();    // B5

        // ---------------- backward zero-init scan (p0_bwd -> xr) -------------
        ull yp1, yp2;
        if (ch == NCH - 1) { yp1 = ylast; yp2 = ylast; }
        else { yp1 = XE[2*(tid+NSP)]; yp2 = XE[2*(tid+NSP)+1]; }
        s0 = 0ull; s1 = 0ull;
        #pragma unroll
        for (int i = CH - 1; i >= 0; --i) {
            ull yv = fma2(RRu[2*i], ss0, fma2(RRu[2*i+1], ss1, xr[i]));
            ull bx = fma2(b2p, yp2, fma2(b1p, yp1, mul2(b0p, yv)));
            yp2 = yp1; yp1 = yv;
            ull ns = fma2(na1p, s0, fma2(na2p, s1, bx));
            s1 = s0; s0 = ns;
            xr[i] = ns;
        }

        // Backward intra-warp KS (descending): hops 1,2,4 chunks.
        v0 = s0; v1 = s1;
        {
            #pragma unroll
            for (int st = 0; st < 3; ++st) {
                const int hc = 1 << st;
                const float* M = PWf + 4 * (hc - 1);
                ull m00 = bc2(M[0]), m01 = bc2(M[1]), m10 = bc2(M[2]), m11 = bc2(M[3]);
                ull u0 = __shfl_down_sync(0xffffffffu, v0, 4 * hc);
                ull u1 = __shfl_down_sync(0xffffffffu, v1, 4 * hc);
                if (g > 7 - hc) { u0 = 0ull; u1 = 0ull; }
                v0 = fma2(m00, u0, fma2(m01, u1, v0));
                v1 = fma2(m10, u0, fma2(m11, u1, v1));
            }
        }
        E0 = __shfl_down_sync(0xffffffffu, v0, 4);
        E1 = __shfl_down_sync(0xffffffffu, v1, 4);
        if (g == 7) { E0 = 0ull; E1 = 0ull; }
        if (g == 0) {
            VWT[(sp * 16 + wrp) * 2]     = v0;
            VWT[(sp * 16 + wrp) * 2 + 1] = v1;
        }
        __syncthreads();    // B6

        // Backward inter-warp combine (mirror).
        if (wrp < 4) {
            int spx = wrp;
            ull w0 = 0ull, w1 = 0ull;
            if (lane < 16) {
                w0 = VWT[(spx * 16 + lane) * 2];
                w1 = VWT[(spx * 16 + lane) * 2 + 1];
            }
            ull cpk = CVu[4 + spx];
            ull a0 = __shfl_down_sync(0xffffffffu, w0, 1);
            ull a1 = __shfl_down_sync(0xffffffffu, w1, 1);
            ull q0 = __shfl_down_sync(0xffffffffu, w0, 2);
            ull q1 = __shfl_down_sync(0xffffffffu, w1, 2);
            if (lane == 14) { q0 = cpk; q1 = cpk; }
            ull m00 = bc2(PKf[0]), m01 = bc2(PKf[1]), m10 = bc2(PKf[2]), m11 = bc2(PKf[3]);
            ull T0 = fma2(m00, q0, fma2(m01, q1, a0));
            ull T1 = fma2(m10, q0, fma2(m11, q1, a1));
            if (lane == 15) { T0 = cpk; T1 = cpk; }
            if (lane < 16) {
                SWT[(spx * 16 + lane) * 2]     = T0;
                SWT[(spx * 16 + lane) * 2 + 1] = T1;
            }
        }
        __syncthreads();    // B7

        // Backward start state: sb = A^(32(7-g))*T'_w + E'_g.
        ull sb0, sb1;
        {
            ull T0 = SWT[(sp * 16 + wrp) * 2], T1 = SWT[(sp * 16 + wrp) * 2 + 1];
            if (g == 7) { sb0 = T0; sb1 = T1; }
            else {
                const float* P = PWf + 4 * (6 - g);
                sb0 = fma2(bc2(P[0]), T0, fma2(bc2(P[1]), T1, E0));
                sb1 = fma2(bc2(P[2]), T0, fma2(bc2(P[3]), T1, E1));
            }
        }

        // Final fix-up + streaming .64 stores.
        ull* osu = (ull*)(out + (size_t)b * Lseq * Dd + (size_t)ch * CH * Dd + d0 + 2 * sp);
        ull* otu = (ull*)(out + OUTT + (size_t)b * Lseq * Dd + (size_t)ch * CH * Dd + d0 + 2 * sp);
        #pragma unroll
        for (int i = 0; i < CH; ++i) {
            ull se = fma2(RRu[2*(CH-1-i)], sb0, fma2(RRu[2*(CH-1-i)+1], sb1, xr[i]));
            ull xv = Yu[tid * YSTRU + i];
            ull tr = fma2(se, neg1p, xv);     // trend = x - seas
            stcs64(osu + (size_t)i * RS, se);
            stcs64(otu + (size_t)i * RS, tr);
        }
    }
}

extern "C" void kernel_launch(void* const* d_in, const int* in_sizes, int n_in,
                              void* d_out, int out_size)
{
    const float* x  = (const float*)d_in[0];
    const float* bcp = (const float*)d_in[1];
    const float* amp = (const float*)d_in[2];
    float* out = (float*)d_out;

    int dev = 0;
    cudaGetDevice(&dev);
    int sms = 148;
    cudaDeviceGetAttribute(&sms, cudaDevAttrMultiProcessorCount, dev);
    if (sms > TILES) sms = TILES;

    const size_t smem = (size_t)SMEM_ULL * sizeof(ull);   // ~143 KB
    cudaFuncSetAttribute(iir_filtfilt_kernel,
                         cudaFuncAttributeMaxDynamicSharedMemorySize, (int)smem);

    iir_filtfilt_kernel<<<sms, NTH, smem>>>(x, bcp, amp, out);
}